// round 6
// baseline (speedup 1.0000x reference)
#include <cuda_runtime.h>
#include <cuda_bf16.h>
#include <cstdint>

#define N_ROWS 4096
#define DIM    512
#define BM 128
#define BN 128
#define BK 64
#define K_ITERS (N_ROWS / BK)            // 64
#define TILE_BYTES (128 * 128)           // 16KB: 128 rows x 128B
#define STAGE_BYTES (2 * TILE_BYTES)
#define STAGES 4
#define SMEM_GRAM (STAGES * STAGE_BYTES + 1024)
#define SMEM_NT   (32 * 513 * 4)         // fp32 tile for norm+transpose

// Scratch: transposed normalized bf16: [mat][d][k], k contiguous
static __device__ __nv_bfloat16 g_normT[4][DIM][N_ROWS];
static __device__ float g_part[88];
static __device__ unsigned int g_ctr;    // zero-init; self-reset by last block

// tile tables: blocks 0..39 = symmetric products (upper triangle), 40..87 = cross
__constant__ int   c_symmat[4] = {3, 0, 1, 2};
__constant__ float c_symw[4]   = {3.f, 1.f, 1.f, 1.f};
__constant__ int   c_ty10[10]  = {0,0,0,0,1,1,1,2,2,3};
__constant__ int   c_tx10[10]  = {0,1,2,3,1,2,3,2,3,3};

// ---------------------------------------------------------------------------
__device__ __forceinline__ uint32_t s2u(const void* p) {
    uint32_t a;
    asm("{ .reg .u64 t; cvta.to.shared.u64 t, %1; cvt.u32.u64 %0, t; }"
        : "=r"(a) : "l"(p));
    return a;
}
__device__ __forceinline__ void cpasync16(uint32_t dst, const void* src) {
    asm volatile("cp.async.cg.shared.global [%0], [%1], 16;" :: "r"(dst), "l"(src) : "memory");
}
__device__ __forceinline__ void ldsm4(uint32_t& r0, uint32_t& r1, uint32_t& r2,
                                      uint32_t& r3, uint32_t addr) {
    asm volatile("ldmatrix.sync.aligned.m8n8.x4.shared.b16 {%0,%1,%2,%3}, [%4];"
                 : "=r"(r0), "=r"(r1), "=r"(r2), "=r"(r3) : "r"(addr));
}
__device__ __forceinline__ void mma16816(float* c, const uint32_t* a, const uint32_t* b) {
    asm volatile(
        "mma.sync.aligned.m16n8k16.row.col.f32.bf16.bf16.f32 "
        "{%0,%1,%2,%3}, {%4,%5,%6,%7}, {%8,%9}, {%0,%1,%2,%3};"
        : "+f"(c[0]), "+f"(c[1]), "+f"(c[2]), "+f"(c[3])
        : "r"(a[0]), "r"(a[1]), "r"(a[2]), "r"(a[3]), "r"(b[0]), "r"(b[1]));
}

// ---------------------------------------------------------------------------
// K1: fused per-row L2 norm + normalize + transpose + bf16 cast.
// ---------------------------------------------------------------------------
__global__ __launch_bounds__(256) void norm_transpose_kernel(
    const float* __restrict__ in0, const float* __restrict__ in1,
    const float* __restrict__ in2, const float* __restrict__ in3)
{
    extern __shared__ float tl[];        // [32][513]
    __shared__ float sinv[32];
    const int mat = blockIdx.y;
    const int kc  = blockIdx.x;          // 0..127 (k-chunk of 32 rows)
    const float* src = (mat == 0) ? in0 : (mat == 1) ? in1 : (mat == 2) ? in2 : in3;
    const int t = threadIdx.x, lane = t & 31, wid = t >> 5;

    const float4* src4 = (const float4*)(src + (size_t)kc * 32 * DIM);
#pragma unroll
    for (int i = 0; i < 16; i++) {
        int idx = t + i * 256;
        int r = idx >> 7, c4 = idx & 127;
        float4 v = src4[idx];
        float* d = &tl[r * 513 + c4 * 4];
        d[0] = v.x; d[1] = v.y; d[2] = v.z; d[3] = v.w;
    }
    __syncthreads();

#pragma unroll
    for (int rr = 0; rr < 4; rr++) {
        int r = wid * 4 + rr;
        float ss = 0.f;
#pragma unroll
        for (int j = 0; j < 16; j++) {
            float v = tl[r * 513 + lane + j * 32];
            ss += v * v;
        }
#pragma unroll
        for (int o = 16; o > 0; o >>= 1) ss += __shfl_xor_sync(0xffffffffu, ss, o);
        if (lane == 0) sinv[r] = rsqrtf(fmaxf(ss, 1e-24f));   // 1/max(||x||,1e-12)
    }
    __syncthreads();

#pragma unroll
    for (int h = 0; h < 2; h++) {
        int d = t + h * 256;
        union { uint32_t u[16]; uint4 v[4]; } pk;
#pragma unroll
        for (int k2 = 0; k2 < 16; k2++) {
            float f0 = tl[(2 * k2    ) * 513 + d] * sinv[2 * k2];
            float f1 = tl[(2 * k2 + 1) * 513 + d] * sinv[2 * k2 + 1];
            __nv_bfloat162 b2 = __floats2bfloat162_rn(f0, f1);
            pk.u[k2] = *(uint32_t*)&b2;
        }
        uint4* dst = (uint4*)&g_normT[mat][d][kc * 32];
#pragma unroll
        for (int q = 0; q < 4; q++) dst[q] = pk.v[q];
    }
}

// ---------------------------------------------------------------------------
// K2: pipelined mma.sync bf16 GEMM tile C[128,128] = A * B^T (K=4096),
//     fused weighted ||C||_F^2 + last-block final reduction.
// 88 blocks, 256 threads = 8 warps: 4 spatial (2x2, 64x64 tiles) x 2 k-groups.
// Group g handles k16-chunks {2g, 2g+1} of each BK=64 slab; partials merged
// through smem before squaring.
// ---------------------------------------------------------------------------
__global__ __launch_bounds__(256, 1) void gram_kernel(float* __restrict__ out)
{
    extern __shared__ char dyn[];
    __shared__ float red[4];
    __shared__ float fr[256];
    __shared__ int s_last;

    const int bid = blockIdx.x;
    int matL, matR, ty, tx; float w;
    if (bid < 40) {
        int p = bid / 10, t = bid % 10;
        matL = matR = c_symmat[p];
        ty = c_ty10[t]; tx = c_tx10[t];
        w = c_symw[p] * ((ty == tx) ? 1.f : 2.f);
    } else {
        int q = bid - 40;
        matL = 3; matR = q >> 4;
        int t = q & 15; ty = t >> 2; tx = t & 3;
        w = -2.f;
    }
    const int m0 = ty * BM, n0 = tx * BN;
    const char* __restrict__ Ab = (const char*)&g_normT[matL][0][0];
    const char* __restrict__ Bb = (const char*)&g_normT[matR][0][0];

    const int tid  = threadIdx.x;
    const int lane = tid & 31;
    const int wid  = tid >> 5;
    const int sp   = wid & 3;            // spatial position (2x2)
    const int grp  = wid >> 2;           // k-group 0/1
    const int warp_m = (sp & 1) * 64;
    const int warp_n = (sp >> 1) * 64;
    const uint32_t dynb = (s2u(dyn) + 1023) & ~1023u;

    // cp.async: 2048 16B chunks per stage (A then B), 8 per thread
    auto issue_loads = [&](int it) {
        uint32_t sbase = dynb + (uint32_t)(it & 3) * STAGE_BYTES;
#pragma unroll
        for (int q = 0; q < 8; q++) {
            int c   = tid + q * 256;
            int isB = c >> 10;
            int row = (c & 1023) >> 3;
            int q16 = c & 7;
            uint32_t sw = (uint32_t)row * 128 + (uint32_t)((q16 ^ (row & 7)) << 4);
            const char* g = (isB ? Bb : Ab)
                          + ((size_t)((isB ? n0 : m0) + row) << 13)   // row * 8192B
                          + (size_t)it * 128 + q16 * 16;
            cpasync16(sbase + (isB ? TILE_BYTES : 0) + sw, g);
        }
        asm volatile("cp.async.commit_group;" ::: "memory");
    };

    // ldmatrix addressing
    uint32_t a_off[4], a_xor[4];
#pragma unroll
    for (int i = 0; i < 4; i++) {
        int row = warp_m + i * 16 + (lane & 15);
        a_off[i] = (uint32_t)row * 128;
        a_xor[i] = (uint32_t)(row & 7);
    }
    const uint32_t a_hi = (uint32_t)(lane >> 4);
    uint32_t b_off[4], b_xor[4];
#pragma unroll
    for (int g = 0; g < 4; g++) {
        int row = warp_n + g * 16 + ((lane >> 4) & 1) * 8 + (lane & 7);
        b_off[g] = (uint32_t)row * 128;
        b_xor[g] = (uint32_t)(row & 7);
    }
    const uint32_t b_hi = (uint32_t)((lane >> 3) & 1);

    float acc[4][8][4];
#pragma unroll
    for (int i = 0; i < 4; i++)
#pragma unroll
        for (int j = 0; j < 8; j++)
#pragma unroll
            for (int r = 0; r < 4; r++) acc[i][j][r] = 0.f;

    issue_loads(0);
    issue_loads(1);
    issue_loads(2);

    for (int it = 0; it < K_ITERS; ++it) {
        if (it <= K_ITERS - 3)
            asm volatile("cp.async.wait_group 2;" ::: "memory");
        else if (it == K_ITERS - 2)
            asm volatile("cp.async.wait_group 1;" ::: "memory");
        else
            asm volatile("cp.async.wait_group 0;" ::: "memory");
        __syncthreads();

        const int nx = it + 3;
        if (nx < K_ITERS) issue_loads(nx);

        const uint32_t sA = dynb + (uint32_t)(it & 3) * STAGE_BYTES;
        const uint32_t sB = sA + TILE_BYTES;

#pragma unroll
        for (int u = 0; u < 2; u++) {                 // this group's 2 k16 chunks
            const int kk = grp * 2 + u;
            const uint32_t ca = (uint32_t)(kk * 2) + a_hi;
            const uint32_t cb = (uint32_t)(kk * 2) + b_hi;
            uint32_t a[4][4];
#pragma unroll
            for (int i = 0; i < 4; i++)
                ldsm4(a[i][0], a[i][1], a[i][2], a[i][3],
                      sA + a_off[i] + ((ca ^ a_xor[i]) << 4));
            uint32_t bf[8][2];
#pragma unroll
            for (int g = 0; g < 4; g++) {
                uint32_t r0, r1, r2, r3;
                ldsm4(r0, r1, r2, r3, sB + b_off[g] + ((cb ^ b_xor[g]) << 4));
                bf[g * 2 + 0][0] = r0; bf[g * 2 + 0][1] = r1;
                bf[g * 2 + 1][0] = r2; bf[g * 2 + 1][1] = r3;
            }
#pragma unroll
            for (int i = 0; i < 4; i++)
#pragma unroll
                for (int j = 0; j < 8; j++)
                    mma16816(acc[i][j], a[i], bf[j]);
        }
    }

    // ---- merge k-group partials through smem, then weighted sum of squares
    float* exch = (float*)dyn;           // 64KB, stages no longer needed
    __syncthreads();
    if (grp == 1) {
#pragma unroll
        for (int i = 0; i < 4; i++)
#pragma unroll
            for (int j = 0; j < 8; j++)
#pragma unroll
                for (int r = 0; r < 4; r++)
                    exch[((sp * 128) + (i * 32 + j * 4 + r)) * 32 + lane] = acc[i][j][r];
    }
    __syncthreads();

    if (grp == 0) {
        float ss = 0.f;
#pragma unroll
        for (int i = 0; i < 4; i++)
#pragma unroll
            for (int j = 0; j < 8; j++)
#pragma unroll
                for (int r = 0; r < 4; r++) {
                    float x = acc[i][j][r]
                            + exch[((sp * 128) + (i * 32 + j * 4 + r)) * 32 + lane];
                    ss += x * x;
                }
#pragma unroll
        for (int o = 16; o > 0; o >>= 1) ss += __shfl_xor_sync(0xffffffffu, ss, o);
        if (lane == 0) red[sp] = ss;
    }
    __syncthreads();
    if (tid == 0) {
        g_part[bid] = w * (red[0] + red[1] + red[2] + red[3]);
        __threadfence();
        unsigned int old = atomicAdd(&g_ctr, 1u);
        s_last = (old == 87u) ? 1 : 0;
    }
    __syncthreads();

    // last finished block: deterministic fixed-order final reduction
    if (s_last) {
        fr[tid] = (tid < 88) ? __ldcg(&g_part[tid]) : 0.f;
        __syncthreads();
#pragma unroll
        for (int o = 128; o > 0; o >>= 1) {
            if (tid < o) fr[tid] += fr[tid + o];
            __syncthreads();
        }
        if (tid == 0) {
            out[0] = fr[0] * (100.0f / 16777216.0f);   // (1/T^2)/N^2
            g_ctr = 0;                                 // self-reset for graph replay
        }
    }
}

// ---------------------------------------------------------------------------
extern "C" void kernel_launch(void* const* d_in, const int* in_sizes, int n_in,
                              void* d_out, int out_size)
{
    const float* rgb   = (const float*)d_in[0];
    const float* depth = (const float*)d_in[1];
    const float* ir    = (const float*)d_in[2];
    const float* tmat  = (const float*)d_in[3];
    float* out = (float*)d_out;

    cudaFuncSetAttribute(norm_transpose_kernel,
                         cudaFuncAttributeMaxDynamicSharedMemorySize, SMEM_NT);
    cudaFuncSetAttribute(gram_kernel,
                         cudaFuncAttributeMaxDynamicSharedMemorySize, SMEM_GRAM);

    dim3 ntgrid(N_ROWS / 32, 4);
    norm_transpose_kernel<<<ntgrid, 256, SMEM_NT>>>(rgb, depth, ir, tmat);

    gram_kernel<<<88, 256, SMEM_GRAM>>>(out);
}

// round 7
// speedup vs baseline: 1.1080x; 1.1080x over previous
#include <cuda_runtime.h>
#include <cuda_bf16.h>
#include <cstdint>

#define N_ROWS 4096
#define DIM    512
#define BK 64
#define K_ITERS (N_ROWS / BK)            // 64
#define TILE_HALF 8192                   // 64 rows x 128B
#define STAGE_BYTES (2 * TILE_HALF)      // A + B = 16KB
#define STAGES 4
#define SMEM_GRAM (STAGES * STAGE_BYTES + 1024)   // 64KB + align
#define SMEM_NT   (32 * 513 * 4)

#define NUNITS 352

// Scratch: transposed normalized bf16: [mat][d][k], k contiguous
static __device__ __nv_bfloat16 g_normT[4][DIM][N_ROWS];
static __device__ float g_part[NUNITS];
static __device__ unsigned int g_ctr;    // zero-init; self-reset by last block

__constant__ int   c_symmat[4] = {3, 0, 1, 2};
__constant__ float c_symw[4]   = {3.f, 1.f, 1.f, 1.f};
__constant__ int   c_ty10[10]  = {0,0,0,0,1,1,1,2,2,3};
__constant__ int   c_tx10[10]  = {0,1,2,3,1,2,3,2,3,3};

// ---------------------------------------------------------------------------
__device__ __forceinline__ uint32_t s2u(const void* p) {
    uint32_t a;
    asm("{ .reg .u64 t; cvta.to.shared.u64 t, %1; cvt.u32.u64 %0, t; }"
        : "=r"(a) : "l"(p));
    return a;
}
__device__ __forceinline__ void cpasync16(uint32_t dst, const void* src) {
    asm volatile("cp.async.cg.shared.global [%0], [%1], 16;" :: "r"(dst), "l"(src) : "memory");
}
__device__ __forceinline__ void ldsm4(uint32_t& r0, uint32_t& r1, uint32_t& r2,
                                      uint32_t& r3, uint32_t addr) {
    asm volatile("ldmatrix.sync.aligned.m8n8.x4.shared.b16 {%0,%1,%2,%3}, [%4];"
                 : "=r"(r0), "=r"(r1), "=r"(r2), "=r"(r3) : "r"(addr));
}
__device__ __forceinline__ void mma16816(float* c, const uint32_t* a, const uint32_t* b) {
    asm volatile(
        "mma.sync.aligned.m16n8k16.row.col.f32.bf16.bf16.f32 "
        "{%0,%1,%2,%3}, {%4,%5,%6,%7}, {%8,%9}, {%0,%1,%2,%3};"
        : "+f"(c[0]), "+f"(c[1]), "+f"(c[2]), "+f"(c[3])
        : "r"(a[0]), "r"(a[1]), "r"(a[2]), "r"(a[3]), "r"(b[0]), "r"(b[1]));
}

// ---------------------------------------------------------------------------
// K1: fused per-row L2 norm + normalize + transpose + bf16 cast.
// ---------------------------------------------------------------------------
__global__ __launch_bounds__(256) void norm_transpose_kernel(
    const float* __restrict__ in0, const float* __restrict__ in1,
    const float* __restrict__ in2, const float* __restrict__ in3)
{
    extern __shared__ float tl[];        // [32][513]
    __shared__ float sinv[32];
    const int mat = blockIdx.y;
    const int kc  = blockIdx.x;          // 0..127
    const float* src = (mat == 0) ? in0 : (mat == 1) ? in1 : (mat == 2) ? in2 : in3;
    const int t = threadIdx.x, lane = t & 31, wid = t >> 5;

    const float4* src4 = (const float4*)(src + (size_t)kc * 32 * DIM);
#pragma unroll
    for (int i = 0; i < 16; i++) {
        int idx = t + i * 256;
        int r = idx >> 7, c4 = idx & 127;
        float4 v = src4[idx];
        float* d = &tl[r * 513 + c4 * 4];
        d[0] = v.x; d[1] = v.y; d[2] = v.z; d[3] = v.w;
    }
    __syncthreads();

#pragma unroll
    for (int rr = 0; rr < 4; rr++) {
        int r = wid * 4 + rr;
        float ss = 0.f;
#pragma unroll
        for (int j = 0; j < 16; j++) {
            float v = tl[r * 513 + lane + j * 32];
            ss += v * v;
        }
#pragma unroll
        for (int o = 16; o > 0; o >>= 1) ss += __shfl_xor_sync(0xffffffffu, ss, o);
        if (lane == 0) sinv[r] = rsqrtf(fmaxf(ss, 1e-24f));
    }
    __syncthreads();

#pragma unroll
    for (int h = 0; h < 2; h++) {
        int d = t + h * 256;
        union { uint32_t u[16]; uint4 v[4]; } pk;
#pragma unroll
        for (int k2 = 0; k2 < 16; k2++) {
            float f0 = tl[(2 * k2    ) * 513 + d] * sinv[2 * k2];
            float f1 = tl[(2 * k2 + 1) * 513 + d] * sinv[2 * k2 + 1];
            __nv_bfloat162 b2 = __floats2bfloat162_rn(f0, f1);
            pk.u[k2] = *(uint32_t*)&b2;
        }
        uint4* dst = (uint4*)&g_normT[mat][d][kc * 32];
#pragma unroll
        for (int q = 0; q < 4; q++) dst[q] = pk.v[q];
    }
}

// ---------------------------------------------------------------------------
// K2: 352 quadrant units (64x64, full K=4096). 128 threads = 4 warps; warp w
// computes the whole 64x64 tile for k16-chunk w of each BK=64 slab.
// Partials merged via smem, then fused weighted ||C||_F^2 + final reduction.
// 2 CTAs co-resident per SM.
// ---------------------------------------------------------------------------
__global__ __launch_bounds__(128, 2) void gram_kernel(float* __restrict__ out)
{
    extern __shared__ char dyn[];
    __shared__ float red[4];
    __shared__ float fr[128];
    __shared__ int s_last;

    // ---- decode unit
    const int bid = blockIdx.x;
    int matL, matR, m0, n0; float w;
    if (bid < 160) {
        int p = bid / 40, rem = bid % 40;
        int t = rem >> 2, quad = rem & 3;
        matL = matR = c_symmat[p];
        int ty = c_ty10[t], tx = c_tx10[t];
        m0 = ty * 128 + (quad >> 1) * 64;
        n0 = tx * 128 + (quad & 1) * 64;
        w = c_symw[p] * ((ty == tx) ? 1.f : 2.f);
    } else {
        int q = bid - 160;
        matL = 3; matR = q / 64;
        int rem = q % 64;
        int t = rem >> 2, quad = rem & 3;
        m0 = (t >> 2) * 128 + (quad >> 1) * 64;
        n0 = (t & 3) * 128 + (quad & 1) * 64;
        w = -2.f;
    }
    const char* __restrict__ Ab = (const char*)&g_normT[matL][0][0];
    const char* __restrict__ Bb = (const char*)&g_normT[matR][0][0];

    const int tid  = threadIdx.x;
    const int lane = tid & 31;
    const int wid  = tid >> 5;           // warp = k16-chunk index (0..3)
    const uint32_t dynb = (s2u(dyn) + 1023) & ~1023u;

    // ---- cp.async: 1024 16B chunks per stage (A 64 rows, B 64 rows), 8/thread
    auto issue_loads = [&](int it) {
        uint32_t sbase = dynb + (uint32_t)(it & 3) * STAGE_BYTES;
#pragma unroll
        for (int q = 0; q < 8; q++) {
            int c   = tid + q * 128;           // 0..1023
            int isB = c >> 9;
            int row = (c & 511) >> 3;          // 0..63
            int q16 = c & 7;
            uint32_t sw = (uint32_t)row * 128 + (uint32_t)((q16 ^ (row & 7)) << 4);
            const char* g = (isB ? Bb : Ab)
                          + ((size_t)((isB ? n0 : m0) + row) << 13)   // row * 8192B
                          + (size_t)it * 128 + q16 * 16;
            cpasync16(sbase + (isB ? TILE_HALF : 0) + sw, g);
        }
        asm volatile("cp.async.commit_group;" ::: "memory");
    };

    // ---- ldmatrix addressing (warp's k16 chunk = wid)
    uint32_t a_off[4], a_xor[4];
#pragma unroll
    for (int i = 0; i < 4; i++) {
        int row = i * 16 + (lane & 15);
        a_off[i] = (uint32_t)row * 128;
        a_xor[i] = (uint32_t)(row & 7);
    }
    const uint32_t ca = (uint32_t)(wid * 2) + (uint32_t)(lane >> 4);
    uint32_t b_off[4], b_xor[4];
#pragma unroll
    for (int g = 0; g < 4; g++) {
        int row = g * 16 + ((lane >> 4) & 1) * 8 + (lane & 7);
        b_off[g] = (uint32_t)row * 128;
        b_xor[g] = (uint32_t)(row & 7);
    }
    const uint32_t cb = (uint32_t)(wid * 2) + (uint32_t)((lane >> 3) & 1);

    float acc[4][8][4];
#pragma unroll
    for (int i = 0; i < 4; i++)
#pragma unroll
        for (int j = 0; j < 8; j++)
#pragma unroll
            for (int r = 0; r < 4; r++) acc[i][j][r] = 0.f;

    issue_loads(0);
    issue_loads(1);
    issue_loads(2);

    for (int it = 0; it < K_ITERS; ++it) {
        if (it <= K_ITERS - 3)
            asm volatile("cp.async.wait_group 2;" ::: "memory");
        else if (it == K_ITERS - 2)
            asm volatile("cp.async.wait_group 1;" ::: "memory");
        else
            asm volatile("cp.async.wait_group 0;" ::: "memory");
        __syncthreads();

        const int nx = it + 3;
        if (nx < K_ITERS) issue_loads(nx);

        const uint32_t sA = dynb + (uint32_t)(it & 3) * STAGE_BYTES;
        const uint32_t sB = sA + TILE_HALF;

        uint32_t a[4][4];
#pragma unroll
        for (int i = 0; i < 4; i++)
            ldsm4(a[i][0], a[i][1], a[i][2], a[i][3],
                  sA + a_off[i] + ((ca ^ a_xor[i]) << 4));
        uint32_t bf[8][2];
#pragma unroll
        for (int g = 0; g < 4; g++) {
            uint32_t r0, r1, r2, r3;
            ldsm4(r0, r1, r2, r3, sB + b_off[g] + ((cb ^ b_xor[g]) << 4));
            bf[g * 2 + 0][0] = r0; bf[g * 2 + 0][1] = r1;
            bf[g * 2 + 1][0] = r2; bf[g * 2 + 1][1] = r3;
        }
#pragma unroll
        for (int i = 0; i < 4; i++)
#pragma unroll
            for (int j = 0; j < 8; j++)
                mma16816(acc[i][j], a[i], bf[j]);
    }

    // ---- merge 4 k-group partials via smem (identical register layouts)
    float* exch = (float*)dyn;           // 64KB, stages done
    __syncthreads();
#pragma unroll
    for (int i = 0; i < 4; i++)
#pragma unroll
        for (int j = 0; j < 8; j++)
#pragma unroll
            for (int r = 0; r < 4; r++)
                exch[wid * 4096 + (i * 32 + j * 4 + r) * 32 + lane] = acc[i][j][r];
    __syncthreads();

    // each thread sums 32 entries across the 4 slabs, squares, accumulates
    float ss = 0.f;
#pragma unroll
    for (int s = 0; s < 32; s++) {
        int f = tid + s * 128;
        float x = exch[f] + exch[4096 + f] + exch[8192 + f] + exch[12288 + f];
        ss += x * x;
    }
#pragma unroll
    for (int o = 16; o > 0; o >>= 1) ss += __shfl_xor_sync(0xffffffffu, ss, o);
    if (lane == 0) red[wid] = ss;
    __syncthreads();
    if (tid == 0) {
        g_part[bid] = w * (red[0] + red[1] + red[2] + red[3]);
        __threadfence();
        unsigned int old = atomicAdd(&g_ctr, 1u);
        s_last = (old == NUNITS - 1) ? 1 : 0;
    }
    __syncthreads();

    // last finished block: deterministic fixed-order final reduction
    if (s_last) {
        float v = __ldcg(&g_part[tid]);
        v += __ldcg(&g_part[tid + 128]);
        if (tid < NUNITS - 256) v += __ldcg(&g_part[tid + 256]);
        fr[tid] = v;
        __syncthreads();
#pragma unroll
        for (int o = 64; o > 0; o >>= 1) {
            if (tid < o) fr[tid] += fr[tid + o];
            __syncthreads();
        }
        if (tid == 0) {
            out[0] = fr[0] * (100.0f / 16777216.0f);   // (1/T^2)/N^2
            g_ctr = 0;                                 // self-reset for graph replay
        }
    }
}

// ---------------------------------------------------------------------------
extern "C" void kernel_launch(void* const* d_in, const int* in_sizes, int n_in,
                              void* d_out, int out_size)
{
    const float* rgb   = (const float*)d_in[0];
    const float* depth = (const float*)d_in[1];
    const float* ir    = (const float*)d_in[2];
    const float* tmat  = (const float*)d_in[3];
    float* out = (float*)d_out;

    cudaFuncSetAttribute(norm_transpose_kernel,
                         cudaFuncAttributeMaxDynamicSharedMemorySize, SMEM_NT);
    cudaFuncSetAttribute(gram_kernel,
                         cudaFuncAttributeMaxDynamicSharedMemorySize, SMEM_GRAM);

    dim3 ntgrid(N_ROWS / 32, 4);
    norm_transpose_kernel<<<ntgrid, 256, SMEM_NT>>>(rgb, depth, ir, tmat);

    gram_kernel<<<NUNITS, 128, SMEM_GRAM>>>(out);
}